// round 10
// baseline (speedup 1.0000x reference)
#include <cuda_runtime.h>
#include <cstdint>

#define N_NODES 50000
#define N_EDGES 800000
#define D 128
#define NCLS 64
#define SCAN_B 1024
#define SCAN_NBLK ((N_NODES + SCAN_B - 1) / SCAN_B)   // 49

// ---------------------------------------------------------------------------
// Device-global scratch
// ---------------------------------------------------------------------------
__device__ __align__(16) float g_y[N_NODES * D];
__device__ __align__(16) float g_h[N_NODES * D];
__device__ int g_row_ptr[N_NODES + 1];
__device__ int g_cursor[N_NODES];
__device__ int g_cnt[N_NODES];
__device__ int g_col[N_EDGES];
__device__ int g_partials[SCAN_NBLK];

// ---------------------------------------------------------------------------
// CSR kernels (unchanged from R9)
// ---------------------------------------------------------------------------
__global__ void __launch_bounds__(256) hist_kernel(
    const int* __restrict__ dst, int* __restrict__ cnt)
{
    int base = (blockIdx.x * blockDim.x + threadIdx.x) * 4;
    if (base + 3 < N_EDGES) {
        int4 d4 = *reinterpret_cast<const int4*>(dst + base);
        atomicAdd(cnt + d4.x, 1);
        atomicAdd(cnt + d4.y, 1);
        atomicAdd(cnt + d4.z, 1);
        atomicAdd(cnt + d4.w, 1);
    } else {
        for (int e = base; e < N_EDGES; e++) atomicAdd(cnt + dst[e], 1);
    }
}

__global__ void __launch_bounds__(SCAN_B) scan_block_kernel(
    const int* __restrict__ cnt, int* __restrict__ row_ptr, int* __restrict__ partials)
{
    __shared__ int wsum[32];
    int i = blockIdx.x * SCAN_B + threadIdx.x;
    int lane = threadIdx.x & 31;
    int wid  = threadIdx.x >> 5;

    int v = (i < N_NODES) ? cnt[i] : 0;
    int x = v;
    #pragma unroll
    for (int off = 1; off < 32; off <<= 1) {
        int t = __shfl_up_sync(0xffffffffu, x, off);
        if (lane >= off) x += t;
    }
    if (lane == 31) wsum[wid] = x;
    __syncthreads();
    if (wid == 0) {
        int w = wsum[lane];
        #pragma unroll
        for (int off = 1; off < 32; off <<= 1) {
            int t = __shfl_up_sync(0xffffffffu, w, off);
            if (lane >= off) w += t;
        }
        wsum[lane] = w;
    }
    __syncthreads();

    int excl = x - v + (wid ? wsum[wid - 1] : 0);
    if (i < N_NODES) row_ptr[i] = excl;
    if (threadIdx.x == SCAN_B - 1) partials[blockIdx.x] = excl + v;
}

__global__ void __launch_bounds__(SCAN_B) scan_add_kernel(
    int* __restrict__ row_ptr, int* __restrict__ cursor, const int* __restrict__ partials)
{
    __shared__ int sp[SCAN_NBLK];
    if (threadIdx.x < SCAN_NBLK) sp[threadIdx.x] = partials[threadIdx.x];
    __syncthreads();
    if (threadIdx.x == 0) {
        int run = 0;
        #pragma unroll
        for (int k = 0; k < SCAN_NBLK; k++) { int t = sp[k]; sp[k] = run; run += t; }
    }
    __syncthreads();

    int i = blockIdx.x * SCAN_B + threadIdx.x;
    if (i < N_NODES) {
        int r = row_ptr[i] + sp[blockIdx.x];
        row_ptr[i] = r;
        cursor[i]  = r;
    }
    if (i == 0) row_ptr[N_NODES] = N_EDGES;
}

__global__ void __launch_bounds__(256) fill_kernel(
    const int* __restrict__ src, const int* __restrict__ dst,
    int* __restrict__ cursor, int* __restrict__ col)
{
    int base = (blockIdx.x * blockDim.x + threadIdx.x) * 4;
    if (base + 3 < N_EDGES) {
        int4 d4 = *reinterpret_cast<const int4*>(dst + base);
        int4 s4 = *reinterpret_cast<const int4*>(src + base);
        int p0 = atomicAdd(cursor + d4.x, 1);
        int p1 = atomicAdd(cursor + d4.y, 1);
        int p2 = atomicAdd(cursor + d4.z, 1);
        int p3 = atomicAdd(cursor + d4.w, 1);
        col[p0] = s4.x; col[p1] = s4.y; col[p2] = s4.z; col[p3] = s4.w;
    } else {
        for (int e = base; e < N_EDGES; e++) {
            int pos = atomicAdd(cursor + dst[e], 1);
            col[pos] = src[e];
        }
    }
}

// ---------------------------------------------------------------------------
// f32x2 GEMM, restructured for occupancy + issue efficiency:
//  - thread tile 4 rows x 16 cols (TX=8, TY=16): acc = 32 ull = 64 regs
//  - K-split (KC=64): smem 51KB
//  - vectorized a-loads (LDS.128 per row per 4 k's)
//  - __launch_bounds__(128, 4): <=128 regs -> 4 blocks/SM = 16 warps/SM
// y[n,j] = sum_k A[n,k] * W[j,k]
// ---------------------------------------------------------------------------
template <int NOUT>
__global__ void __launch_bounds__(128, 4) gemm_kernel(
    const float* __restrict__ A, const float* __restrict__ W, float* __restrict__ y)
{
    constexpr int BM  = 64;
    constexpr int KC  = 64;
    constexpr int TX  = NOUT / 16;       // 8 (NOUT=128) or 4 (NOUT=64)
    constexpr int TY  = 128 / TX;        // 16 or 32
    constexpr int RPT = BM / TY;         // 4 or 2
    constexpr int SXS = KC + 4;          // 68
    constexpr int SWS = NOUT + 4;        // 132 or 68

    extern __shared__ float smem[];
    float* sX = smem;                    // [BM][SXS]
    float* sW = smem + BM * SXS;         // [KC][SWS]

    const int tid  = threadIdx.x;
    const int row0 = blockIdx.x * BM;

    const int tx = tid % TX;
    const int ty = tid / TX;
    const int cbase = tx * 16;
    const int rbase = ty * RPT;

    unsigned long long acc[RPT][8];
    #pragma unroll
    for (int r = 0; r < RPT; r++)
        #pragma unroll
        for (int c = 0; c < 8; c++) acc[r][c] = 0ULL;

    #pragma unroll
    for (int kc = 0; kc < D; kc += KC) {
        // X tile chunk [BM][KC]
        #pragma unroll
        for (int i = tid; i < BM * (KC / 4); i += 128) {
            int r  = i >> 4;
            int c4 = i & 15;
            int gr = row0 + r;
            float4 v = make_float4(0.f, 0.f, 0.f, 0.f);
            if (gr < N_NODES)
                v = *reinterpret_cast<const float4*>(A + (size_t)gr * D + kc + c4 * 4);
            reinterpret_cast<float4*>(sX + r * SXS)[c4] = v;
        }
        // W chunk transposed into sW[k][n]
        #pragma unroll
        for (int i = tid; i < NOUT * (KC / 4); i += 128) {
            int n  = i >> 4;
            int k4 = i & 15;
            float4 v = *reinterpret_cast<const float4*>(W + (size_t)n * D + kc + k4 * 4);
            sW[(k4 * 4 + 0) * SWS + n] = v.x;
            sW[(k4 * 4 + 1) * SWS + n] = v.y;
            sW[(k4 * 4 + 2) * SWS + n] = v.z;
            sW[(k4 * 4 + 3) * SWS + n] = v.w;
        }
        __syncthreads();

        #pragma unroll
        for (int k4 = 0; k4 < KC; k4 += 4) {
            // vector a-load: 4 k's per row in one LDS.128
            float4 av[RPT];
            #pragma unroll
            for (int r = 0; r < RPT; r++)
                av[r] = *reinterpret_cast<const float4*>(sX + (rbase + r) * SXS + k4);

            #pragma unroll
            for (int kk = 0; kk < 4; kk++) {
                const ulonglong2* bp =
                    reinterpret_cast<const ulonglong2*>(sW + (k4 + kk) * SWS + cbase);
                ulonglong2 b0 = bp[0];
                ulonglong2 b1 = bp[1];
                ulonglong2 b2 = bp[2];
                ulonglong2 b3 = bp[3];
                #pragma unroll
                for (int r = 0; r < RPT; r++) {
                    float a = (kk == 0) ? av[r].x : (kk == 1) ? av[r].y
                            : (kk == 2) ? av[r].z : av[r].w;
                    unsigned long long a2;
                    asm("mov.b64 %0, {%1, %1};" : "=l"(a2) : "f"(a));
                    asm("fma.rn.f32x2 %0, %1, %2, %0;" : "+l"(acc[r][0]) : "l"(a2), "l"(b0.x));
                    asm("fma.rn.f32x2 %0, %1, %2, %0;" : "+l"(acc[r][1]) : "l"(a2), "l"(b0.y));
                    asm("fma.rn.f32x2 %0, %1, %2, %0;" : "+l"(acc[r][2]) : "l"(a2), "l"(b1.x));
                    asm("fma.rn.f32x2 %0, %1, %2, %0;" : "+l"(acc[r][3]) : "l"(a2), "l"(b1.y));
                    asm("fma.rn.f32x2 %0, %1, %2, %0;" : "+l"(acc[r][4]) : "l"(a2), "l"(b2.x));
                    asm("fma.rn.f32x2 %0, %1, %2, %0;" : "+l"(acc[r][5]) : "l"(a2), "l"(b2.y));
                    asm("fma.rn.f32x2 %0, %1, %2, %0;" : "+l"(acc[r][6]) : "l"(a2), "l"(b3.x));
                    asm("fma.rn.f32x2 %0, %1, %2, %0;" : "+l"(acc[r][7]) : "l"(a2), "l"(b3.y));
                }
            }
        }
        __syncthreads();
    }

    #pragma unroll
    for (int r = 0; r < RPT; r++) {
        int row = row0 + rbase + r;
        if (row >= N_NODES) continue;
        float o[16];
        #pragma unroll
        for (int c = 0; c < 8; c++)
            asm("mov.b64 {%0, %1}, %2;" : "=f"(o[2*c]), "=f"(o[2*c+1]) : "l"(acc[r][c]));
        float4* dst4 = reinterpret_cast<float4*>(y + (size_t)row * NOUT + cbase);
        dst4[0] = make_float4(o[0],  o[1],  o[2],  o[3]);
        dst4[1] = make_float4(o[4],  o[5],  o[6],  o[7]);
        dst4[2] = make_float4(o[8],  o[9],  o[10], o[11]);
        dst4[3] = make_float4(o[12], o[13], o[14], o[15]);
    }
}

// ---------------------------------------------------------------------------
// CSR aggregation + bias + relu (unchanged from R9: unroll-4, warp per node)
// ---------------------------------------------------------------------------
__global__ void __launch_bounds__(256) aggregate128_kernel(
    const float* __restrict__ y, const int* __restrict__ row_ptr,
    const int* __restrict__ col, const float* __restrict__ bias,
    float* __restrict__ out)
{
    int node = (blockIdx.x * blockDim.x + threadIdx.x) >> 5;
    int lane = threadIdx.x & 31;
    if (node >= N_NODES) return;

    int beg = __ldg(row_ptr + node);
    int end = __ldg(row_ptr + node + 1);

    const float4* base = reinterpret_cast<const float4*>(y);
    float4 acc = base[(size_t)node * 32 + lane];
    float4 acc2 = make_float4(0.f, 0.f, 0.f, 0.f);

    int j = beg;
    for (; j + 3 < end; j += 4) {
        int c0 = __ldg(col + j);
        int c1 = __ldg(col + j + 1);
        int c2 = __ldg(col + j + 2);
        int c3 = __ldg(col + j + 3);
        float4 v0 = base[(size_t)c0 * 32 + lane];
        float4 v1 = base[(size_t)c1 * 32 + lane];
        float4 v2 = base[(size_t)c2 * 32 + lane];
        float4 v3 = base[(size_t)c3 * 32 + lane];
        acc.x  += v0.x; acc.y  += v0.y; acc.z  += v0.z; acc.w  += v0.w;
        acc2.x += v1.x; acc2.y += v1.y; acc2.z += v1.z; acc2.w += v1.w;
        acc.x  += v2.x; acc.y  += v2.y; acc.z  += v2.z; acc.w  += v2.w;
        acc2.x += v3.x; acc2.y += v3.y; acc2.z += v3.z; acc2.w += v3.w;
    }
    for (; j < end; j++) {
        int c0 = __ldg(col + j);
        float4 v0 = base[(size_t)c0 * 32 + lane];
        acc.x += v0.x; acc.y += v0.y; acc.z += v0.z; acc.w += v0.w;
    }
    acc.x += acc2.x; acc.y += acc2.y; acc.z += acc2.z; acc.w += acc2.w;

    float4 b = reinterpret_cast<const float4*>(bias)[lane];
    float4 o;
    o.x = fmaxf(acc.x + b.x, 0.f);
    o.y = fmaxf(acc.y + b.y, 0.f);
    o.z = fmaxf(acc.z + b.z, 0.f);
    o.w = fmaxf(acc.w + b.w, 0.f);
    reinterpret_cast<float4*>(out)[(size_t)node * 32 + lane] = o;
}

__global__ void __launch_bounds__(256) aggregate64_kernel(
    const float* __restrict__ y, const int* __restrict__ row_ptr,
    const int* __restrict__ col, const float* __restrict__ bias,
    float* __restrict__ out)
{
    int node = (blockIdx.x * blockDim.x + threadIdx.x) >> 5;
    int lane = threadIdx.x & 31;
    if (node >= N_NODES) return;

    int beg = __ldg(row_ptr + node);
    int end = __ldg(row_ptr + node + 1);

    const float2* base = reinterpret_cast<const float2*>(y);
    float2 acc = base[(size_t)node * 32 + lane];
    float2 acc2 = make_float2(0.f, 0.f);

    int j = beg;
    for (; j + 3 < end; j += 4) {
        int c0 = __ldg(col + j);
        int c1 = __ldg(col + j + 1);
        int c2 = __ldg(col + j + 2);
        int c3 = __ldg(col + j + 3);
        float2 v0 = base[(size_t)c0 * 32 + lane];
        float2 v1 = base[(size_t)c1 * 32 + lane];
        float2 v2 = base[(size_t)c2 * 32 + lane];
        float2 v3 = base[(size_t)c3 * 32 + lane];
        acc.x  += v0.x; acc.y  += v0.y;
        acc2.x += v1.x; acc2.y += v1.y;
        acc.x  += v2.x; acc.y  += v2.y;
        acc2.x += v3.x; acc2.y += v3.y;
    }
    for (; j < end; j++) {
        int c0 = __ldg(col + j);
        float2 v0 = base[(size_t)c0 * 32 + lane];
        acc.x += v0.x; acc.y += v0.y;
    }
    acc.x += acc2.x; acc.y += acc2.y;

    float2 b = reinterpret_cast<const float2*>(bias)[lane];
    float2 o;
    o.x = fmaxf(acc.x + b.x, 0.f);
    o.y = fmaxf(acc.y + b.y, 0.f);
    reinterpret_cast<float2*>(out)[(size_t)node * 32 + lane] = o;
}

// ---------------------------------------------------------------------------
// Launch: single stream, gemm1 in slot 4 (ncu lands there)
// ---------------------------------------------------------------------------
extern "C" void kernel_launch(void* const* d_in, const int* in_sizes, int n_in,
                              void* d_out, int out_size)
{
    const float* in_feat = (const float*)d_in[0];
    const float* W1 = (const float*)d_in[1];
    const float* b1 = (const float*)d_in[2];
    const float* W2 = (const float*)d_in[3];
    const float* b2 = (const float*)d_in[4];
    const float* W3 = (const float*)d_in[5];
    const float* b3 = (const float*)d_in[6];
    const int*   src = (const int*)d_in[7];
    const int*   dst = (const int*)d_in[8];
    float* out = (float*)d_out;

    float *y, *h;
    int *row_ptr, *cursor, *cnt, *col, *partials;
    cudaGetSymbolAddress((void**)&y, g_y);
    cudaGetSymbolAddress((void**)&h, g_h);
    cudaGetSymbolAddress((void**)&row_ptr, g_row_ptr);
    cudaGetSymbolAddress((void**)&cursor, g_cursor);
    cudaGetSymbolAddress((void**)&cnt, g_cnt);
    cudaGetSymbolAddress((void**)&col, g_col);
    cudaGetSymbolAddress((void**)&partials, g_partials);

    const int smem128 = (64 * (64 + 4) + 64 * (128 + 4)) * (int)sizeof(float);  // ~51KB
    const int smem64  = (64 * (64 + 4) + 64 * (64 + 4))  * (int)sizeof(float);  // ~35KB
    cudaFuncSetAttribute(gemm_kernel<128>,
                         cudaFuncAttributeMaxDynamicSharedMemorySize, smem128);
    cudaFuncSetAttribute(gemm_kernel<64>,
                         cudaFuncAttributeMaxDynamicSharedMemorySize, smem64);

    const int edge4_blocks = (N_EDGES / 4 + 255) / 256;
    const int gemm_blocks  = (N_NODES + 63) / 64;
    const int agg_blocks   = (N_NODES * 32 + 255) / 256;

    // ---- CSR + layer-1 GEMM ----
    cudaMemsetAsync(cnt, 0, N_NODES * sizeof(int), 0);
    hist_kernel<<<edge4_blocks, 256>>>(dst, cnt);                       // 1
    scan_block_kernel<<<SCAN_NBLK, SCAN_B>>>(cnt, row_ptr, partials);   // 2
    scan_add_kernel<<<SCAN_NBLK, SCAN_B>>>(row_ptr, cursor, partials);  // 3
    gemm_kernel<128><<<gemm_blocks, 128, smem128>>>(in_feat, W1, y);    // 4 <- ncu
    fill_kernel<<<edge4_blocks, 256>>>(src, dst, cursor, col);          // 5

    // ---- Layer 1 boundary: h = relu(y + Ay + b1) ----
    aggregate128_kernel<<<agg_blocks, 256>>>(y, row_ptr, col, b1, h);   // 6

    // ---- Layer 2: y = h @ W2 ; h = relu(y + Ay + b2) ----
    gemm_kernel<128><<<gemm_blocks, 128, smem128>>>(h, W2, y);          // 7
    aggregate128_kernel<<<agg_blocks, 256>>>(y, row_ptr, col, b2, h);   // 8

    // ---- Layer 3: y = h @ W3 (64) ; out = relu(y + Ay + b3) ----
    gemm_kernel<64><<<gemm_blocks, 128, smem64>>>(h, W3, y);            // 9
    aggregate64_kernel<<<agg_blocks, 256>>>(y, row_ptr, col, b3, out);  // 10
}

// round 11
// speedup vs baseline: 1.4941x; 1.4941x over previous
#include <cuda_runtime.h>
#include <cstdint>

#define N_NODES 50000
#define N_EDGES 800000
#define D 128
#define NCLS 64
#define SCAN_B 1024
#define SCAN_NBLK ((N_NODES + SCAN_B - 1) / SCAN_B)   // 49

// ---------------------------------------------------------------------------
// Device-global scratch
// ---------------------------------------------------------------------------
__device__ __align__(16) float g_y[N_NODES * D];
__device__ __align__(16) float g_h[N_NODES * D];
__device__ int g_row_ptr[N_NODES + 1];
__device__ int g_cursor[N_NODES];
__device__ int g_cnt[N_NODES];
__device__ int g_col[N_EDGES];
__device__ int g_partials[SCAN_NBLK];

// ---------------------------------------------------------------------------
// CSR kernels (unchanged from R9)
// ---------------------------------------------------------------------------
__global__ void __launch_bounds__(256) hist_kernel(
    const int* __restrict__ dst, int* __restrict__ cnt)
{
    int base = (blockIdx.x * blockDim.x + threadIdx.x) * 4;
    if (base + 3 < N_EDGES) {
        int4 d4 = *reinterpret_cast<const int4*>(dst + base);
        atomicAdd(cnt + d4.x, 1);
        atomicAdd(cnt + d4.y, 1);
        atomicAdd(cnt + d4.z, 1);
        atomicAdd(cnt + d4.w, 1);
    } else {
        for (int e = base; e < N_EDGES; e++) atomicAdd(cnt + dst[e], 1);
    }
}

__global__ void __launch_bounds__(SCAN_B) scan_block_kernel(
    const int* __restrict__ cnt, int* __restrict__ row_ptr, int* __restrict__ partials)
{
    __shared__ int wsum[32];
    int i = blockIdx.x * SCAN_B + threadIdx.x;
    int lane = threadIdx.x & 31;
    int wid  = threadIdx.x >> 5;

    int v = (i < N_NODES) ? cnt[i] : 0;
    int x = v;
    #pragma unroll
    for (int off = 1; off < 32; off <<= 1) {
        int t = __shfl_up_sync(0xffffffffu, x, off);
        if (lane >= off) x += t;
    }
    if (lane == 31) wsum[wid] = x;
    __syncthreads();
    if (wid == 0) {
        int w = wsum[lane];
        #pragma unroll
        for (int off = 1; off < 32; off <<= 1) {
            int t = __shfl_up_sync(0xffffffffu, w, off);
            if (lane >= off) w += t;
        }
        wsum[lane] = w;
    }
    __syncthreads();

    int excl = x - v + (wid ? wsum[wid - 1] : 0);
    if (i < N_NODES) row_ptr[i] = excl;
    if (threadIdx.x == SCAN_B - 1) partials[blockIdx.x] = excl + v;
}

__global__ void __launch_bounds__(SCAN_B) scan_add_kernel(
    int* __restrict__ row_ptr, int* __restrict__ cursor, const int* __restrict__ partials)
{
    __shared__ int sp[SCAN_NBLK];
    if (threadIdx.x < SCAN_NBLK) sp[threadIdx.x] = partials[threadIdx.x];
    __syncthreads();
    if (threadIdx.x == 0) {
        int run = 0;
        #pragma unroll
        for (int k = 0; k < SCAN_NBLK; k++) { int t = sp[k]; sp[k] = run; run += t; }
    }
    __syncthreads();

    int i = blockIdx.x * SCAN_B + threadIdx.x;
    if (i < N_NODES) {
        int r = row_ptr[i] + sp[blockIdx.x];
        row_ptr[i] = r;
        cursor[i]  = r;
    }
    if (i == 0) row_ptr[N_NODES] = N_EDGES;
}

__global__ void __launch_bounds__(256) fill_kernel(
    const int* __restrict__ src, const int* __restrict__ dst,
    int* __restrict__ cursor, int* __restrict__ col)
{
    int base = (blockIdx.x * blockDim.x + threadIdx.x) * 4;
    if (base + 3 < N_EDGES) {
        int4 d4 = *reinterpret_cast<const int4*>(dst + base);
        int4 s4 = *reinterpret_cast<const int4*>(src + base);
        int p0 = atomicAdd(cursor + d4.x, 1);
        int p1 = atomicAdd(cursor + d4.y, 1);
        int p2 = atomicAdd(cursor + d4.z, 1);
        int p3 = atomicAdd(cursor + d4.w, 1);
        col[p0] = s4.x; col[p1] = s4.y; col[p2] = s4.z; col[p3] = s4.w;
    } else {
        for (int e = base; e < N_EDGES; e++) {
            int pos = atomicAdd(cursor + dst[e], 1);
            col[pos] = src[e];
        }
    }
}

// ---------------------------------------------------------------------------
// f32x2 GEMM with ROW-PAIRED lanes (zero duplication MOVs in the inner loop):
//   - X stored TRANSPOSED in smem (sXT[k][r]) -> a-pair (A[r][k],A[r+1][k])
//     loads as one LDS.64 directly.
//   - W stored DUPLICATED in smem (each w as (w,w) pair), chunk-interleaved
//     by tx so each LDS.128 warp access covers 64 consecutive words.
//   - Per k, per thread (NOUT=128): 4 LDS.64 + 4 LDS.128 + 32 FMA2 = 40 instr
//     (vs 58 in the col-paired version).
//   - KC=32 K-chunks; smem 42KB (gemm128) / 26KB (gemm64).
// y[n,j] = sum_k A[n,k] * W[j,k].  BM=64 rows/block, 128 threads,
// thread tile = 8 rows x 8 cols (gemm128) or 4 rows x 8 cols (gemm64).
// ---------------------------------------------------------------------------
template <int NOUT>
__global__ void __launch_bounds__(128, 3) gemm_kernel(
    const float* __restrict__ A, const float* __restrict__ W, float* __restrict__ y)
{
    constexpr int BM    = 64;
    constexpr int KC    = 32;
    constexpr int TX    = NOUT / 8;       // 16 (128) or 8 (64)
    constexpr int TY    = 128 / TX;       // 8 or 16
    constexpr int RPT   = BM / TY;        // 8 or 4
    constexpr int NP    = RPT / 2;        // row pairs: 4 or 2
    constexpr int SXTS  = BM + 2;         // 66 (even -> LDS.64 aligned)
    constexpr int SW2S  = 2 * NOUT + 8;   // 264 or 136 (16B aligned)
    constexpr int CW    = NOUT / 2;       // words per chunk per k: 64 or 32
    constexpr int COLC  = NOUT / 4;       // cols per chunk: 32 or 16

    extern __shared__ float smem[];
    float* sXT = smem;                    // [KC][SXTS]  transposed X chunk
    float* sW2 = smem + KC * SXTS;        // [KC][SW2S]  duplicated W chunk

    const int tid  = threadIdx.x;
    const int row0 = blockIdx.x * BM;
    const int tx   = tid % TX;
    const int ty   = tid / TX;
    const int rbase = ty * RPT;           // even (RPT is 8 or 4)

    unsigned long long acc[NP][8];
    #pragma unroll
    for (int p = 0; p < NP; p++)
        #pragma unroll
        for (int c = 0; c < 8; c++) acc[p][c] = 0ULL;

    #pragma unroll
    for (int kc = 0; kc < D; kc += KC) {
        // --- X chunk -> sXT transposed ---
        #pragma unroll
        for (int i = tid; i < BM * (KC / 4); i += 128) {
            int r  = i >> 3;              // KC/4 == 8
            int c4 = i & 7;
            int gr = row0 + r;
            float4 v = make_float4(0.f, 0.f, 0.f, 0.f);
            if (gr < N_NODES)
                v = *reinterpret_cast<const float4*>(A + (size_t)gr * D + kc + c4 * 4);
            int k0 = c4 * 4;
            sXT[(k0 + 0) * SXTS + r] = v.x;
            sXT[(k0 + 1) * SXTS + r] = v.y;
            sXT[(k0 + 2) * SXTS + r] = v.z;
            sXT[(k0 + 3) * SXTS + r] = v.w;
        }
        // --- W chunk -> sW2 duplicated, chunk-interleaved ---
        #pragma unroll
        for (int i = tid; i < NOUT * (KC / 4); i += 128) {
            int n  = i >> 3;
            int k4 = i & 7;
            float4 v = *reinterpret_cast<const float4*>(W + (size_t)n * D + kc + k4 * 4);
            int off = (n / COLC) * CW + ((n % COLC) >> 1) * 4 + (n & 1) * 2;
            int k0 = k4 * 4;
            float* w0 = sW2 + (k0 + 0) * SW2S + off;  w0[0] = v.x; w0[1] = v.x;
            float* w1 = sW2 + (k0 + 1) * SW2S + off;  w1[0] = v.y; w1[1] = v.y;
            float* w2 = sW2 + (k0 + 2) * SW2S + off;  w2[0] = v.z; w2[1] = v.z;
            float* w3 = sW2 + (k0 + 3) * SW2S + off;  w3[0] = v.w; w3[1] = v.w;
        }
        __syncthreads();

        #pragma unroll 8
        for (int k = 0; k < KC; k++) {
            const float* swk = sW2 + k * SW2S + tx * 4;
            ulonglong2 b0 = *reinterpret_cast<const ulonglong2*>(swk + 0 * CW);
            ulonglong2 b1 = *reinterpret_cast<const ulonglong2*>(swk + 1 * CW);
            ulonglong2 b2 = *reinterpret_cast<const ulonglong2*>(swk + 2 * CW);
            ulonglong2 b3 = *reinterpret_cast<const ulonglong2*>(swk + 3 * CW);
            const float* sxk = sXT + k * SXTS + rbase;
            unsigned long long a[NP];
            #pragma unroll
            for (int p = 0; p < NP; p++)
                a[p] = *reinterpret_cast<const unsigned long long*>(sxk + 2 * p);
            #pragma unroll
            for (int p = 0; p < NP; p++) {
                asm("fma.rn.f32x2 %0, %1, %2, %0;" : "+l"(acc[p][0]) : "l"(a[p]), "l"(b0.x));
                asm("fma.rn.f32x2 %0, %1, %2, %0;" : "+l"(acc[p][1]) : "l"(a[p]), "l"(b0.y));
                asm("fma.rn.f32x2 %0, %1, %2, %0;" : "+l"(acc[p][2]) : "l"(a[p]), "l"(b1.x));
                asm("fma.rn.f32x2 %0, %1, %2, %0;" : "+l"(acc[p][3]) : "l"(a[p]), "l"(b1.y));
                asm("fma.rn.f32x2 %0, %1, %2, %0;" : "+l"(acc[p][4]) : "l"(a[p]), "l"(b2.x));
                asm("fma.rn.f32x2 %0, %1, %2, %0;" : "+l"(acc[p][5]) : "l"(a[p]), "l"(b2.y));
                asm("fma.rn.f32x2 %0, %1, %2, %0;" : "+l"(acc[p][6]) : "l"(a[p]), "l"(b3.x));
                asm("fma.rn.f32x2 %0, %1, %2, %0;" : "+l"(acc[p][7]) : "l"(a[p]), "l"(b3.y));
            }
        }
        __syncthreads();
    }

    // Output: acc[p][2c], acc[p][2c+1] hold cols (colbase, colbase+1) for the
    // row pair (lo = row rbase+2p, hi = row rbase+2p+1).
    #pragma unroll
    for (int p = 0; p < NP; p++) {
        int r0 = row0 + rbase + 2 * p;
        int r1 = r0 + 1;
        #pragma unroll
        for (int c = 0; c < 4; c++) {
            float lo0, hi0, lo1, hi1;
            asm("mov.b64 {%0, %1}, %2;" : "=f"(lo0), "=f"(hi0) : "l"(acc[p][2*c]));
            asm("mov.b64 {%0, %1}, %2;" : "=f"(lo1), "=f"(hi1) : "l"(acc[p][2*c+1]));
            int colbase = c * COLC + 2 * tx;
            if (r0 < N_NODES)
                *reinterpret_cast<float2*>(y + (size_t)r0 * NOUT + colbase) = make_float2(lo0, lo1);
            if (r1 < N_NODES)
                *reinterpret_cast<float2*>(y + (size_t)r1 * NOUT + colbase) = make_float2(hi0, hi1);
        }
    }
}

// ---------------------------------------------------------------------------
// CSR aggregation + bias + relu (unchanged from R9: unroll-4, warp per node)
// ---------------------------------------------------------------------------
__global__ void __launch_bounds__(256) aggregate128_kernel(
    const float* __restrict__ y, const int* __restrict__ row_ptr,
    const int* __restrict__ col, const float* __restrict__ bias,
    float* __restrict__ out)
{
    int node = (blockIdx.x * blockDim.x + threadIdx.x) >> 5;
    int lane = threadIdx.x & 31;
    if (node >= N_NODES) return;

    int beg = __ldg(row_ptr + node);
    int end = __ldg(row_ptr + node + 1);

    const float4* base = reinterpret_cast<const float4*>(y);
    float4 acc = base[(size_t)node * 32 + lane];
    float4 acc2 = make_float4(0.f, 0.f, 0.f, 0.f);

    int j = beg;
    for (; j + 3 < end; j += 4) {
        int c0 = __ldg(col + j);
        int c1 = __ldg(col + j + 1);
        int c2 = __ldg(col + j + 2);
        int c3 = __ldg(col + j + 3);
        float4 v0 = base[(size_t)c0 * 32 + lane];
        float4 v1 = base[(size_t)c1 * 32 + lane];
        float4 v2 = base[(size_t)c2 * 32 + lane];
        float4 v3 = base[(size_t)c3 * 32 + lane];
        acc.x  += v0.x; acc.y  += v0.y; acc.z  += v0.z; acc.w  += v0.w;
        acc2.x += v1.x; acc2.y += v1.y; acc2.z += v1.z; acc2.w += v1.w;
        acc.x  += v2.x; acc.y  += v2.y; acc.z  += v2.z; acc.w  += v2.w;
        acc2.x += v3.x; acc2.y += v3.y; acc2.z += v3.z; acc2.w += v3.w;
    }
    for (; j < end; j++) {
        int c0 = __ldg(col + j);
        float4 v0 = base[(size_t)c0 * 32 + lane];
        acc.x += v0.x; acc.y += v0.y; acc.z += v0.z; acc.w += v0.w;
    }
    acc.x += acc2.x; acc.y += acc2.y; acc.z += acc2.z; acc.w += acc2.w;

    float4 b = reinterpret_cast<const float4*>(bias)[lane];
    float4 o;
    o.x = fmaxf(acc.x + b.x, 0.f);
    o.y = fmaxf(acc.y + b.y, 0.f);
    o.z = fmaxf(acc.z + b.z, 0.f);
    o.w = fmaxf(acc.w + b.w, 0.f);
    reinterpret_cast<float4*>(out)[(size_t)node * 32 + lane] = o;
}

__global__ void __launch_bounds__(256) aggregate64_kernel(
    const float* __restrict__ y, const int* __restrict__ row_ptr,
    const int* __restrict__ col, const float* __restrict__ bias,
    float* __restrict__ out)
{
    int node = (blockIdx.x * blockDim.x + threadIdx.x) >> 5;
    int lane = threadIdx.x & 31;
    if (node >= N_NODES) return;

    int beg = __ldg(row_ptr + node);
    int end = __ldg(row_ptr + node + 1);

    const float2* base = reinterpret_cast<const float2*>(y);
    float2 acc = base[(size_t)node * 32 + lane];
    float2 acc2 = make_float2(0.f, 0.f);

    int j = beg;
    for (; j + 3 < end; j += 4) {
        int c0 = __ldg(col + j);
        int c1 = __ldg(col + j + 1);
        int c2 = __ldg(col + j + 2);
        int c3 = __ldg(col + j + 3);
        float2 v0 = base[(size_t)c0 * 32 + lane];
        float2 v1 = base[(size_t)c1 * 32 + lane];
        float2 v2 = base[(size_t)c2 * 32 + lane];
        float2 v3 = base[(size_t)c3 * 32 + lane];
        acc.x  += v0.x; acc.y  += v0.y;
        acc2.x += v1.x; acc2.y += v1.y;
        acc.x  += v2.x; acc.y  += v2.y;
        acc2.x += v3.x; acc2.y += v3.y;
    }
    for (; j < end; j++) {
        int c0 = __ldg(col + j);
        float2 v0 = base[(size_t)c0 * 32 + lane];
        acc.x += v0.x; acc.y += v0.y;
    }
    acc.x += acc2.x; acc.y += acc2.y;

    float2 b = reinterpret_cast<const float2*>(bias)[lane];
    float2 o;
    o.x = fmaxf(acc.x + b.x, 0.f);
    o.y = fmaxf(acc.y + b.y, 0.f);
    reinterpret_cast<float2*>(out)[(size_t)node * 32 + lane] = o;
}

// ---------------------------------------------------------------------------
// Launch: single stream, gemm1 in slot 4 (ncu lands there)
// ---------------------------------------------------------------------------
extern "C" void kernel_launch(void* const* d_in, const int* in_sizes, int n_in,
                              void* d_out, int out_size)
{
    const float* in_feat = (const float*)d_in[0];
    const float* W1 = (const float*)d_in[1];
    const float* b1 = (const float*)d_in[2];
    const float* W2 = (const float*)d_in[3];
    const float* b2 = (const float*)d_in[4];
    const float* W3 = (const float*)d_in[5];
    const float* b3 = (const float*)d_in[6];
    const int*   src = (const int*)d_in[7];
    const int*   dst = (const int*)d_in[8];
    float* out = (float*)d_out;

    float *y, *h;
    int *row_ptr, *cursor, *cnt, *col, *partials;
    cudaGetSymbolAddress((void**)&y, g_y);
    cudaGetSymbolAddress((void**)&h, g_h);
    cudaGetSymbolAddress((void**)&row_ptr, g_row_ptr);
    cudaGetSymbolAddress((void**)&cursor, g_cursor);
    cudaGetSymbolAddress((void**)&cnt, g_cnt);
    cudaGetSymbolAddress((void**)&col, g_col);
    cudaGetSymbolAddress((void**)&partials, g_partials);

    const int smem128 = (32 * (64 + 2) + 32 * (256 + 8)) * (int)sizeof(float);  // ~42KB
    const int smem64  = (32 * (64 + 2) + 32 * (128 + 8)) * (int)sizeof(float);  // ~26KB
    cudaFuncSetAttribute(gemm_kernel<128>,
                         cudaFuncAttributeMaxDynamicSharedMemorySize, smem128);
    cudaFuncSetAttribute(gemm_kernel<64>,
                         cudaFuncAttributeMaxDynamicSharedMemorySize, smem64);

    const int edge4_blocks = (N_EDGES / 4 + 255) / 256;
    const int gemm_blocks  = (N_NODES + 63) / 64;
    const int agg_blocks   = (N_NODES * 32 + 255) / 256;

    // ---- CSR + layer-1 GEMM ----
    cudaMemsetAsync(cnt, 0, N_NODES * sizeof(int), 0);
    hist_kernel<<<edge4_blocks, 256>>>(dst, cnt);                       // 1
    scan_block_kernel<<<SCAN_NBLK, SCAN_B>>>(cnt, row_ptr, partials);   // 2
    scan_add_kernel<<<SCAN_NBLK, SCAN_B>>>(row_ptr, cursor, partials);  // 3
    gemm_kernel<128><<<gemm_blocks, 128, smem128>>>(in_feat, W1, y);    // 4 <- ncu
    fill_kernel<<<edge4_blocks, 256>>>(src, dst, cursor, col);          // 5

    // ---- Layer 1 boundary: h = relu(y + Ay + b1) ----
    aggregate128_kernel<<<agg_blocks, 256>>>(y, row_ptr, col, b1, h);   // 6

    // ---- Layer 2: y = h @ W2 ; h = relu(y + Ay + b2) ----
    gemm_kernel<128><<<gemm_blocks, 128, smem128>>>(h, W2, y);          // 7
    aggregate128_kernel<<<agg_blocks, 256>>>(y, row_ptr, col, b2, h);   // 8

    // ---- Layer 3: y = h @ W3 (64) ; out = relu(y + Ay + b3) ----
    gemm_kernel<64><<<gemm_blocks, 128, smem64>>>(h, W3, y);            // 9
    aggregate64_kernel<<<agg_blocks, 256>>>(y, row_ptr, col, b3, out);  // 10
}

// round 12
// speedup vs baseline: 1.6258x; 1.0882x over previous
#include <cuda_runtime.h>
#include <cstdint>

#define N_NODES 50000
#define N_EDGES 800000
#define D 128
#define NCLS 64
#define SCAN_B 1024
#define SCAN_NBLK ((N_NODES + SCAN_B - 1) / SCAN_B)   // 49

// ---------------------------------------------------------------------------
// Device-global scratch
// ---------------------------------------------------------------------------
__device__ __align__(16) float g_y[N_NODES * D];
__device__ __align__(16) float g_h[N_NODES * D];
__device__ int g_row_ptr[N_NODES + 1];
__device__ int g_cursor[N_NODES];
__device__ int g_cnt[N_NODES];
__device__ int g_col[N_EDGES];
__device__ int g_partials[SCAN_NBLK];

// ---------------------------------------------------------------------------
// CSR kernels (unchanged from R9)
// ---------------------------------------------------------------------------
__global__ void __launch_bounds__(256) hist_kernel(
    const int* __restrict__ dst, int* __restrict__ cnt)
{
    int base = (blockIdx.x * blockDim.x + threadIdx.x) * 4;
    if (base + 3 < N_EDGES) {
        int4 d4 = *reinterpret_cast<const int4*>(dst + base);
        atomicAdd(cnt + d4.x, 1);
        atomicAdd(cnt + d4.y, 1);
        atomicAdd(cnt + d4.z, 1);
        atomicAdd(cnt + d4.w, 1);
    } else {
        for (int e = base; e < N_EDGES; e++) atomicAdd(cnt + dst[e], 1);
    }
}

__global__ void __launch_bounds__(SCAN_B) scan_block_kernel(
    const int* __restrict__ cnt, int* __restrict__ row_ptr, int* __restrict__ partials)
{
    __shared__ int wsum[32];
    int i = blockIdx.x * SCAN_B + threadIdx.x;
    int lane = threadIdx.x & 31;
    int wid  = threadIdx.x >> 5;

    int v = (i < N_NODES) ? cnt[i] : 0;
    int x = v;
    #pragma unroll
    for (int off = 1; off < 32; off <<= 1) {
        int t = __shfl_up_sync(0xffffffffu, x, off);
        if (lane >= off) x += t;
    }
    if (lane == 31) wsum[wid] = x;
    __syncthreads();
    if (wid == 0) {
        int w = wsum[lane];
        #pragma unroll
        for (int off = 1; off < 32; off <<= 1) {
            int t = __shfl_up_sync(0xffffffffu, w, off);
            if (lane >= off) w += t;
        }
        wsum[lane] = w;
    }
    __syncthreads();

    int excl = x - v + (wid ? wsum[wid - 1] : 0);
    if (i < N_NODES) row_ptr[i] = excl;
    if (threadIdx.x == SCAN_B - 1) partials[blockIdx.x] = excl + v;
}

__global__ void __launch_bounds__(SCAN_B) scan_add_kernel(
    int* __restrict__ row_ptr, int* __restrict__ cursor, const int* __restrict__ partials)
{
    __shared__ int sp[SCAN_NBLK];
    if (threadIdx.x < SCAN_NBLK) sp[threadIdx.x] = partials[threadIdx.x];
    __syncthreads();
    if (threadIdx.x == 0) {
        int run = 0;
        #pragma unroll
        for (int k = 0; k < SCAN_NBLK; k++) { int t = sp[k]; sp[k] = run; run += t; }
    }
    __syncthreads();

    int i = blockIdx.x * SCAN_B + threadIdx.x;
    if (i < N_NODES) {
        int r = row_ptr[i] + sp[blockIdx.x];
        row_ptr[i] = r;
        cursor[i]  = r;
    }
    if (i == 0) row_ptr[N_NODES] = N_EDGES;
}

__global__ void __launch_bounds__(256) fill_kernel(
    const int* __restrict__ src, const int* __restrict__ dst,
    int* __restrict__ cursor, int* __restrict__ col)
{
    int base = (blockIdx.x * blockDim.x + threadIdx.x) * 4;
    if (base + 3 < N_EDGES) {
        int4 d4 = *reinterpret_cast<const int4*>(dst + base);
        int4 s4 = *reinterpret_cast<const int4*>(src + base);
        int p0 = atomicAdd(cursor + d4.x, 1);
        int p1 = atomicAdd(cursor + d4.y, 1);
        int p2 = atomicAdd(cursor + d4.z, 1);
        int p3 = atomicAdd(cursor + d4.w, 1);
        col[p0] = s4.x; col[p1] = s4.y; col[p2] = s4.z; col[p3] = s4.w;
    } else {
        for (int e = base; e < N_EDGES; e++) {
            int pos = atomicAdd(cursor + dst[e], 1);
            col[pos] = src[e];
        }
    }
}

// ---------------------------------------------------------------------------
// f32x2 GEMM — R9's exact tile (BM=64, KC=64, 128 thr, 8 rows x 8 cols), with
// the ONE change: __launch_bounds__(128, 3) caps regs at 170 so a 3rd block
// fits per SM (12 warps vs 8). R9's natural 210 regs were mostly optional
// LDS pipelining slack; live state (~130) fits 170 without spilling.
// y[n,j] = sum_k A[n,k] * W[j,k]
// ---------------------------------------------------------------------------
template <int NOUT>
__global__ void __launch_bounds__(128, 3) gemm_kernel(
    const float* __restrict__ A, const float* __restrict__ W, float* __restrict__ y)
{
    constexpr int BM  = 64;
    constexpr int KC  = 64;              // K chunk
    constexpr int TX  = NOUT / 8;        // 16 or 8
    constexpr int TY  = 128 / TX;        // 8 or 16
    constexpr int RPT = BM / TY;         // 8 or 4
    constexpr int SXS = KC + 4;          // 68
    constexpr int SWS = NOUT + 4;        // 132 or 68

    extern __shared__ float smem[];
    float* sX = smem;                    // [BM][SXS]
    float* sW = smem + BM * SXS;         // [KC][SWS]  (W chunk, transposed)

    const int tid  = threadIdx.x;
    const int row0 = blockIdx.x * BM;

    const int tx = tid % TX;
    const int ty = tid / TX;
    const int cbase = tx * 8;
    const int rbase = ty * RPT;

    unsigned long long acc[RPT][4];
    #pragma unroll
    for (int r = 0; r < RPT; r++)
        #pragma unroll
        for (int c = 0; c < 4; c++) acc[r][c] = 0ULL;

    #pragma unroll
    for (int kc = 0; kc < D; kc += KC) {
        // X tile chunk: [BM][KC], coalesced float4 loads
        #pragma unroll
        for (int i = tid; i < BM * (KC / 4); i += 128) {
            int r  = i >> 4;             // KC/4 == 16
            int c4 = i & 15;
            int gr = row0 + r;
            float4 v = make_float4(0.f, 0.f, 0.f, 0.f);
            if (gr < N_NODES)
                v = *reinterpret_cast<const float4*>(A + (size_t)gr * D + kc + c4 * 4);
            reinterpret_cast<float4*>(sX + r * SXS)[c4] = v;
        }
        // W chunk: rows n, cols [kc, kc+KC), transposed into sW[k][n]
        #pragma unroll
        for (int i = tid; i < NOUT * (KC / 4); i += 128) {
            int n  = i >> 4;
            int k4 = i & 15;
            float4 v = *reinterpret_cast<const float4*>(W + (size_t)n * D + kc + k4 * 4);
            sW[(k4 * 4 + 0) * SWS + n] = v.x;
            sW[(k4 * 4 + 1) * SWS + n] = v.y;
            sW[(k4 * 4 + 2) * SWS + n] = v.z;
            sW[(k4 * 4 + 3) * SWS + n] = v.w;
        }
        __syncthreads();

        #pragma unroll 4
        for (int k = 0; k < KC; k++) {
            const ulonglong2* bp = reinterpret_cast<const ulonglong2*>(sW + k * SWS + cbase);
            ulonglong2 bA = bp[0];
            ulonglong2 bB = bp[1];
            #pragma unroll
            for (int r = 0; r < RPT; r++) {
                float a = sX[(rbase + r) * SXS + k];
                unsigned long long a2;
                asm("mov.b64 %0, {%1, %1};" : "=l"(a2) : "f"(a));
                asm("fma.rn.f32x2 %0, %1, %2, %0;" : "+l"(acc[r][0]) : "l"(a2), "l"(bA.x));
                asm("fma.rn.f32x2 %0, %1, %2, %0;" : "+l"(acc[r][1]) : "l"(a2), "l"(bA.y));
                asm("fma.rn.f32x2 %0, %1, %2, %0;" : "+l"(acc[r][2]) : "l"(a2), "l"(bB.x));
                asm("fma.rn.f32x2 %0, %1, %2, %0;" : "+l"(acc[r][3]) : "l"(a2), "l"(bB.y));
            }
        }
        __syncthreads();
    }

    #pragma unroll
    for (int r = 0; r < RPT; r++) {
        int row = row0 + rbase + r;
        if (row >= N_NODES) continue;
        float o[8];
        #pragma unroll
        for (int c = 0; c < 4; c++)
            asm("mov.b64 {%0, %1}, %2;" : "=f"(o[2*c]), "=f"(o[2*c+1]) : "l"(acc[r][c]));
        float4* dst4 = reinterpret_cast<float4*>(y + (size_t)row * NOUT + cbase);
        dst4[0] = make_float4(o[0], o[1], o[2], o[3]);
        dst4[1] = make_float4(o[4], o[5], o[6], o[7]);
    }
}

// ---------------------------------------------------------------------------
// CSR aggregation + bias + relu (unchanged: unroll-4, warp per node)
// ---------------------------------------------------------------------------
__global__ void __launch_bounds__(256) aggregate128_kernel(
    const float* __restrict__ y, const int* __restrict__ row_ptr,
    const int* __restrict__ col, const float* __restrict__ bias,
    float* __restrict__ out)
{
    int node = (blockIdx.x * blockDim.x + threadIdx.x) >> 5;
    int lane = threadIdx.x & 31;
    if (node >= N_NODES) return;

    int beg = __ldg(row_ptr + node);
    int end = __ldg(row_ptr + node + 1);

    const float4* base = reinterpret_cast<const float4*>(y);
    float4 acc = base[(size_t)node * 32 + lane];
    float4 acc2 = make_float4(0.f, 0.f, 0.f, 0.f);

    int j = beg;
    for (; j + 3 < end; j += 4) {
        int c0 = __ldg(col + j);
        int c1 = __ldg(col + j + 1);
        int c2 = __ldg(col + j + 2);
        int c3 = __ldg(col + j + 3);
        float4 v0 = base[(size_t)c0 * 32 + lane];
        float4 v1 = base[(size_t)c1 * 32 + lane];
        float4 v2 = base[(size_t)c2 * 32 + lane];
        float4 v3 = base[(size_t)c3 * 32 + lane];
        acc.x  += v0.x; acc.y  += v0.y; acc.z  += v0.z; acc.w  += v0.w;
        acc2.x += v1.x; acc2.y += v1.y; acc2.z += v1.z; acc2.w += v1.w;
        acc.x  += v2.x; acc.y  += v2.y; acc.z  += v2.z; acc.w  += v2.w;
        acc2.x += v3.x; acc2.y += v3.y; acc2.z += v3.z; acc2.w += v3.w;
    }
    for (; j < end; j++) {
        int c0 = __ldg(col + j);
        float4 v0 = base[(size_t)c0 * 32 + lane];
        acc.x += v0.x; acc.y += v0.y; acc.z += v0.z; acc.w += v0.w;
    }
    acc.x += acc2.x; acc.y += acc2.y; acc.z += acc2.z; acc.w += acc2.w;

    float4 b = reinterpret_cast<const float4*>(bias)[lane];
    float4 o;
    o.x = fmaxf(acc.x + b.x, 0.f);
    o.y = fmaxf(acc.y + b.y, 0.f);
    o.z = fmaxf(acc.z + b.z, 0.f);
    o.w = fmaxf(acc.w + b.w, 0.f);
    reinterpret_cast<float4*>(out)[(size_t)node * 32 + lane] = o;
}

__global__ void __launch_bounds__(256) aggregate64_kernel(
    const float* __restrict__ y, const int* __restrict__ row_ptr,
    const int* __restrict__ col, const float* __restrict__ bias,
    float* __restrict__ out)
{
    int node = (blockIdx.x * blockDim.x + threadIdx.x) >> 5;
    int lane = threadIdx.x & 31;
    if (node >= N_NODES) return;

    int beg = __ldg(row_ptr + node);
    int end = __ldg(row_ptr + node + 1);

    const float2* base = reinterpret_cast<const float2*>(y);
    float2 acc = base[(size_t)node * 32 + lane];
    float2 acc2 = make_float2(0.f, 0.f);

    int j = beg;
    for (; j + 3 < end; j += 4) {
        int c0 = __ldg(col + j);
        int c1 = __ldg(col + j + 1);
        int c2 = __ldg(col + j + 2);
        int c3 = __ldg(col + j + 3);
        float2 v0 = base[(size_t)c0 * 32 + lane];
        float2 v1 = base[(size_t)c1 * 32 + lane];
        float2 v2 = base[(size_t)c2 * 32 + lane];
        float2 v3 = base[(size_t)c3 * 32 + lane];
        acc.x  += v0.x; acc.y  += v0.y;
        acc2.x += v1.x; acc2.y += v1.y;
        acc.x  += v2.x; acc.y  += v2.y;
        acc2.x += v3.x; acc2.y += v3.y;
    }
    for (; j < end; j++) {
        int c0 = __ldg(col + j);
        float2 v0 = base[(size_t)c0 * 32 + lane];
        acc.x += v0.x; acc.y += v0.y;
    }
    acc.x += acc2.x; acc.y += acc2.y;

    float2 b = reinterpret_cast<const float2*>(bias)[lane];
    float2 o;
    o.x = fmaxf(acc.x + b.x, 0.f);
    o.y = fmaxf(acc.y + b.y, 0.f);
    reinterpret_cast<float2*>(out)[(size_t)node * 32 + lane] = o;
}

// ---------------------------------------------------------------------------
// Launch: single stream, gemm1 in slot 4 (ncu lands there)
// ---------------------------------------------------------------------------
extern "C" void kernel_launch(void* const* d_in, const int* in_sizes, int n_in,
                              void* d_out, int out_size)
{
    const float* in_feat = (const float*)d_in[0];
    const float* W1 = (const float*)d_in[1];
    const float* b1 = (const float*)d_in[2];
    const float* W2 = (const float*)d_in[3];
    const float* b2 = (const float*)d_in[4];
    const float* W3 = (const float*)d_in[5];
    const float* b3 = (const float*)d_in[6];
    const int*   src = (const int*)d_in[7];
    const int*   dst = (const int*)d_in[8];
    float* out = (float*)d_out;

    float *y, *h;
    int *row_ptr, *cursor, *cnt, *col, *partials;
    cudaGetSymbolAddress((void**)&y, g_y);
    cudaGetSymbolAddress((void**)&h, g_h);
    cudaGetSymbolAddress((void**)&row_ptr, g_row_ptr);
    cudaGetSymbolAddress((void**)&cursor, g_cursor);
    cudaGetSymbolAddress((void**)&cnt, g_cnt);
    cudaGetSymbolAddress((void**)&col, g_col);
    cudaGetSymbolAddress((void**)&partials, g_partials);

    const int smem128 = (64 * (64 + 4) + 64 * (128 + 4)) * (int)sizeof(float);  // ~51KB
    const int smem64  = (64 * (64 + 4) + 64 * (64 + 4))  * (int)sizeof(float);  // ~35KB
    cudaFuncSetAttribute(gemm_kernel<128>,
                         cudaFuncAttributeMaxDynamicSharedMemorySize, smem128);
    cudaFuncSetAttribute(gemm_kernel<64>,
                         cudaFuncAttributeMaxDynamicSharedMemorySize, smem64);

    const int edge4_blocks = (N_EDGES / 4 + 255) / 256;
    const int gemm_blocks  = (N_NODES + 63) / 64;
    const int agg_blocks   = (N_NODES * 32 + 255) / 256;

    // ---- CSR + layer-1 GEMM ----
    cudaMemsetAsync(cnt, 0, N_NODES * sizeof(int), 0);
    hist_kernel<<<edge4_blocks, 256>>>(dst, cnt);                       // 1
    scan_block_kernel<<<SCAN_NBLK, SCAN_B>>>(cnt, row_ptr, partials);   // 2
    scan_add_kernel<<<SCAN_NBLK, SCAN_B>>>(row_ptr, cursor, partials);  // 3
    gemm_kernel<128><<<gemm_blocks, 128, smem128>>>(in_feat, W1, y);    // 4 <- ncu
    fill_kernel<<<edge4_blocks, 256>>>(src, dst, cursor, col);          // 5

    // ---- Layer 1 boundary: h = relu(y + Ay + b1) ----
    aggregate128_kernel<<<agg_blocks, 256>>>(y, row_ptr, col, b1, h);   // 6

    // ---- Layer 2: y = h @ W2 ; h = relu(y + Ay + b2) ----
    gemm_kernel<128><<<gemm_blocks, 128, smem128>>>(h, W2, y);          // 7
    aggregate128_kernel<<<agg_blocks, 256>>>(y, row_ptr, col, b2, h);   // 8

    // ---- Layer 3: y = h @ W3 (64) ; out = relu(y + Ay + b3) ----
    gemm_kernel<64><<<gemm_blocks, 128, smem64>>>(h, W3, y);            // 9
    aggregate64_kernel<<<agg_blocks, 256>>>(y, row_ptr, col, b3, out);  // 10
}

// round 13
// speedup vs baseline: 1.8009x; 1.1077x over previous
#include <cuda_runtime.h>
#include <cstdint>

#define N_NODES 50000
#define N_EDGES 800000
#define D 128
#define NCLS 64
#define SCAN_B 1024
#define SCAN_NBLK ((N_NODES + SCAN_B - 1) / SCAN_B)   // 49

// ---------------------------------------------------------------------------
// Device-global scratch
// ---------------------------------------------------------------------------
__device__ __align__(16) float g_y[N_NODES * D];
__device__ __align__(16) float g_h[N_NODES * D];
__device__ int g_row_ptr[N_NODES + 1];
__device__ int g_cursor[N_NODES];
__device__ int g_cnt[N_NODES];
__device__ int g_col[N_EDGES];
__device__ int g_partials[SCAN_NBLK];

// ---------------------------------------------------------------------------
// CSR kernels (unchanged)
// ---------------------------------------------------------------------------
__global__ void __launch_bounds__(256) hist_kernel(
    const int* __restrict__ dst, int* __restrict__ cnt)
{
    int base = (blockIdx.x * blockDim.x + threadIdx.x) * 4;
    if (base + 3 < N_EDGES) {
        int4 d4 = *reinterpret_cast<const int4*>(dst + base);
        atomicAdd(cnt + d4.x, 1);
        atomicAdd(cnt + d4.y, 1);
        atomicAdd(cnt + d4.z, 1);
        atomicAdd(cnt + d4.w, 1);
    } else {
        for (int e = base; e < N_EDGES; e++) atomicAdd(cnt + dst[e], 1);
    }
}

__global__ void __launch_bounds__(SCAN_B) scan_block_kernel(
    const int* __restrict__ cnt, int* __restrict__ row_ptr, int* __restrict__ partials)
{
    __shared__ int wsum[32];
    int i = blockIdx.x * SCAN_B + threadIdx.x;
    int lane = threadIdx.x & 31;
    int wid  = threadIdx.x >> 5;

    int v = (i < N_NODES) ? cnt[i] : 0;
    int x = v;
    #pragma unroll
    for (int off = 1; off < 32; off <<= 1) {
        int t = __shfl_up_sync(0xffffffffu, x, off);
        if (lane >= off) x += t;
    }
    if (lane == 31) wsum[wid] = x;
    __syncthreads();
    if (wid == 0) {
        int w = wsum[lane];
        #pragma unroll
        for (int off = 1; off < 32; off <<= 1) {
            int t = __shfl_up_sync(0xffffffffu, w, off);
            if (lane >= off) w += t;
        }
        wsum[lane] = w;
    }
    __syncthreads();

    int excl = x - v + (wid ? wsum[wid - 1] : 0);
    if (i < N_NODES) row_ptr[i] = excl;
    if (threadIdx.x == SCAN_B - 1) partials[blockIdx.x] = excl + v;
}

__global__ void __launch_bounds__(SCAN_B) scan_add_kernel(
    int* __restrict__ row_ptr, int* __restrict__ cursor, const int* __restrict__ partials)
{
    __shared__ int sp[SCAN_NBLK];
    if (threadIdx.x < SCAN_NBLK) sp[threadIdx.x] = partials[threadIdx.x];
    __syncthreads();
    if (threadIdx.x == 0) {
        int run = 0;
        #pragma unroll
        for (int k = 0; k < SCAN_NBLK; k++) { int t = sp[k]; sp[k] = run; run += t; }
    }
    __syncthreads();

    int i = blockIdx.x * SCAN_B + threadIdx.x;
    if (i < N_NODES) {
        int r = row_ptr[i] + sp[blockIdx.x];
        row_ptr[i] = r;
        cursor[i]  = r;
    }
    if (i == 0) row_ptr[N_NODES] = N_EDGES;
}

__global__ void __launch_bounds__(256) fill_kernel(
    const int* __restrict__ src, const int* __restrict__ dst,
    int* __restrict__ cursor, int* __restrict__ col)
{
    int base = (blockIdx.x * blockDim.x + threadIdx.x) * 4;
    if (base + 3 < N_EDGES) {
        int4 d4 = *reinterpret_cast<const int4*>(dst + base);
        int4 s4 = *reinterpret_cast<const int4*>(src + base);
        int p0 = atomicAdd(cursor + d4.x, 1);
        int p1 = atomicAdd(cursor + d4.y, 1);
        int p2 = atomicAdd(cursor + d4.z, 1);
        int p3 = atomicAdd(cursor + d4.w, 1);
        col[p0] = s4.x; col[p1] = s4.y; col[p2] = s4.z; col[p3] = s4.w;
    } else {
        for (int e = base; e < N_EDGES; e++) {
            int pos = atomicAdd(cursor + dst[e], 1);
            col[pos] = src[e];
        }
    }
}

// ---------------------------------------------------------------------------
// f32x2 GEMM — R12 tile (BM=64, KC=64, 128 thr, 8r x 8c, lb(128,3)) with two
// LDS-wavefront reductions (R12 profile showed l1tex 67.8% = binding pipe):
//  1. a-loads vectorized over k: one LDS.128 per row per 4 k's (was 4 LDS.32)
//  2. b columns split as {tx*4..+3} U {NOUT/2+tx*4..+3}: each 8-thread phase
//     covers banks 0-31 exactly once -> conflict-free (was 2-way at tx*8)
// y[n,j] = sum_k A[n,k] * W[j,k]
// ---------------------------------------------------------------------------
template <int NOUT>
__global__ void __launch_bounds__(128, 3) gemm_kernel(
    const float* __restrict__ A, const float* __restrict__ W, float* __restrict__ y)
{
    constexpr int BM   = 64;
    constexpr int KC   = 64;
    constexpr int TX   = NOUT / 8;        // 16 or 8
    constexpr int TY   = 128 / TX;        // 8 or 16
    constexpr int RPT  = BM / TY;         // 8 or 4
    constexpr int SXS  = KC + 4;          // 68 (68%4==0 -> float4-aligned rows)
    constexpr int SWS  = NOUT + 4;        // 132 or 68
    constexpr int HALF = NOUT / 2;        // 64 or 32

    extern __shared__ float smem[];
    float* sX = smem;                     // [BM][SXS]
    float* sW = smem + BM * SXS;          // [KC][SWS]  (W chunk, transposed)

    const int tid  = threadIdx.x;
    const int row0 = blockIdx.x * BM;

    const int tx = tid % TX;
    const int ty = tid / TX;
    const int cb0 = tx * 4;               // first 4-col group
    const int cb1 = HALF + tx * 4;        // second 4-col group
    const int rbase = ty * RPT;

    // acc[r][0..1] -> cols cb0..cb0+3 ; acc[r][2..3] -> cols cb1..cb1+3
    unsigned long long acc[RPT][4];
    #pragma unroll
    for (int r = 0; r < RPT; r++)
        #pragma unroll
        for (int c = 0; c < 4; c++) acc[r][c] = 0ULL;

    #pragma unroll
    for (int kc = 0; kc < D; kc += KC) {
        // X tile chunk: [BM][KC], coalesced float4 loads
        #pragma unroll
        for (int i = tid; i < BM * (KC / 4); i += 128) {
            int r  = i >> 4;              // KC/4 == 16
            int c4 = i & 15;
            int gr = row0 + r;
            float4 v = make_float4(0.f, 0.f, 0.f, 0.f);
            if (gr < N_NODES)
                v = *reinterpret_cast<const float4*>(A + (size_t)gr * D + kc + c4 * 4);
            reinterpret_cast<float4*>(sX + r * SXS)[c4] = v;
        }
        // W chunk transposed into sW[k][n]
        #pragma unroll
        for (int i = tid; i < NOUT * (KC / 4); i += 128) {
            int n  = i >> 4;
            int k4 = i & 15;
            float4 v = *reinterpret_cast<const float4*>(W + (size_t)n * D + kc + k4 * 4);
            sW[(k4 * 4 + 0) * SWS + n] = v.x;
            sW[(k4 * 4 + 1) * SWS + n] = v.y;
            sW[(k4 * 4 + 2) * SWS + n] = v.z;
            sW[(k4 * 4 + 3) * SWS + n] = v.w;
        }
        __syncthreads();

        #pragma unroll 2
        for (int k4 = 0; k4 < KC; k4 += 4) {
            // a: one LDS.128 per row covering 4 k's (broadcast across tx)
            float4 av[RPT];
            #pragma unroll
            for (int r = 0; r < RPT; r++)
                av[r] = *reinterpret_cast<const float4*>(sX + (rbase + r) * SXS + k4);

            #pragma unroll
            for (int kk = 0; kk < 4; kk++) {
                const float* swk = sW + (k4 + kk) * SWS;
                ulonglong2 b0 = *reinterpret_cast<const ulonglong2*>(swk + cb0);
                ulonglong2 b1 = *reinterpret_cast<const ulonglong2*>(swk + cb1);
                #pragma unroll
                for (int r = 0; r < RPT; r++) {
                    float a = (kk == 0) ? av[r].x : (kk == 1) ? av[r].y
                            : (kk == 2) ? av[r].z : av[r].w;
                    unsigned long long a2;
                    asm("mov.b64 %0, {%1, %1};" : "=l"(a2) : "f"(a));
                    asm("fma.rn.f32x2 %0, %1, %2, %0;" : "+l"(acc[r][0]) : "l"(a2), "l"(b0.x));
                    asm("fma.rn.f32x2 %0, %1, %2, %0;" : "+l"(acc[r][1]) : "l"(a2), "l"(b0.y));
                    asm("fma.rn.f32x2 %0, %1, %2, %0;" : "+l"(acc[r][2]) : "l"(a2), "l"(b1.x));
                    asm("fma.rn.f32x2 %0, %1, %2, %0;" : "+l"(acc[r][3]) : "l"(a2), "l"(b1.y));
                }
            }
        }
        __syncthreads();
    }

    #pragma unroll
    for (int r = 0; r < RPT; r++) {
        int row = row0 + rbase + r;
        if (row >= N_NODES) continue;
        float o[8];
        #pragma unroll
        for (int c = 0; c < 4; c++)
            asm("mov.b64 {%0, %1}, %2;" : "=f"(o[2*c]), "=f"(o[2*c+1]) : "l"(acc[r][c]));
        *reinterpret_cast<float4*>(y + (size_t)row * NOUT + cb0) =
            make_float4(o[0], o[1], o[2], o[3]);
        *reinterpret_cast<float4*>(y + (size_t)row * NOUT + cb1) =
            make_float4(o[4], o[5], o[6], o[7]);
    }
}

// ---------------------------------------------------------------------------
// CSR aggregation + bias + relu (unchanged: unroll-4, warp per node)
// ---------------------------------------------------------------------------
__global__ void __launch_bounds__(256) aggregate128_kernel(
    const float* __restrict__ y, const int* __restrict__ row_ptr,
    const int* __restrict__ col, const float* __restrict__ bias,
    float* __restrict__ out)
{
    int node = (blockIdx.x * blockDim.x + threadIdx.x) >> 5;
    int lane = threadIdx.x & 31;
    if (node >= N_NODES) return;

    int beg = __ldg(row_ptr + node);
    int end = __ldg(row_ptr + node + 1);

    const float4* base = reinterpret_cast<const float4*>(y);
    float4 acc = base[(size_t)node * 32 + lane];
    float4 acc2 = make_float4(0.f, 0.f, 0.f, 0.f);

    int j = beg;
    for (; j + 3 < end; j += 4) {
        int c0 = __ldg(col + j);
        int c1 = __ldg(col + j + 1);
        int c2 = __ldg(col + j + 2);
        int c3 = __ldg(col + j + 3);
        float4 v0 = base[(size_t)c0 * 32 + lane];
        float4 v1 = base[(size_t)c1 * 32 + lane];
        float4 v2 = base[(size_t)c2 * 32 + lane];
        float4 v3 = base[(size_t)c3 * 32 + lane];
        acc.x  += v0.x; acc.y  += v0.y; acc.z  += v0.z; acc.w  += v0.w;
        acc2.x += v1.x; acc2.y += v1.y; acc2.z += v1.z; acc2.w += v1.w;
        acc.x  += v2.x; acc.y  += v2.y; acc.z  += v2.z; acc.w  += v2.w;
        acc2.x += v3.x; acc2.y += v3.y; acc2.z += v3.z; acc2.w += v3.w;
    }
    for (; j < end; j++) {
        int c0 = __ldg(col + j);
        float4 v0 = base[(size_t)c0 * 32 + lane];
        acc.x += v0.x; acc.y += v0.y; acc.z += v0.z; acc.w += v0.w;
    }
    acc.x += acc2.x; acc.y += acc2.y; acc.z += acc2.z; acc.w += acc2.w;

    float4 b = reinterpret_cast<const float4*>(bias)[lane];
    float4 o;
    o.x = fmaxf(acc.x + b.x, 0.f);
    o.y = fmaxf(acc.y + b.y, 0.f);
    o.z = fmaxf(acc.z + b.z, 0.f);
    o.w = fmaxf(acc.w + b.w, 0.f);
    reinterpret_cast<float4*>(out)[(size_t)node * 32 + lane] = o;
}

__global__ void __launch_bounds__(256) aggregate64_kernel(
    const float* __restrict__ y, const int* __restrict__ row_ptr,
    const int* __restrict__ col, const float* __restrict__ bias,
    float* __restrict__ out)
{
    int node = (blockIdx.x * blockDim.x + threadIdx.x) >> 5;
    int lane = threadIdx.x & 31;
    if (node >= N_NODES) return;

    int beg = __ldg(row_ptr + node);
    int end = __ldg(row_ptr + node + 1);

    const float2* base = reinterpret_cast<const float2*>(y);
    float2 acc = base[(size_t)node * 32 + lane];
    float2 acc2 = make_float2(0.f, 0.f);

    int j = beg;
    for (; j + 3 < end; j += 4) {
        int c0 = __ldg(col + j);
        int c1 = __ldg(col + j + 1);
        int c2 = __ldg(col + j + 2);
        int c3 = __ldg(col + j + 3);
        float2 v0 = base[(size_t)c0 * 32 + lane];
        float2 v1 = base[(size_t)c1 * 32 + lane];
        float2 v2 = base[(size_t)c2 * 32 + lane];
        float2 v3 = base[(size_t)c3 * 32 + lane];
        acc.x  += v0.x; acc.y  += v0.y;
        acc2.x += v1.x; acc2.y += v1.y;
        acc.x  += v2.x; acc.y  += v2.y;
        acc2.x += v3.x; acc2.y += v3.y;
    }
    for (; j < end; j++) {
        int c0 = __ldg(col + j);
        float2 v0 = base[(size_t)c0 * 32 + lane];
        acc.x += v0.x; acc.y += v0.y;
    }
    acc.x += acc2.x; acc.y += acc2.y;

    float2 b = reinterpret_cast<const float2*>(bias)[lane];
    float2 o;
    o.x = fmaxf(acc.x + b.x, 0.f);
    o.y = fmaxf(acc.y + b.y, 0.f);
    reinterpret_cast<float2*>(out)[(size_t)node * 32 + lane] = o;
}

// ---------------------------------------------------------------------------
// Launch: single stream, gemm1 in slot 4 (ncu lands there)
// ---------------------------------------------------------------------------
extern "C" void kernel_launch(void* const* d_in, const int* in_sizes, int n_in,
                              void* d_out, int out_size)
{
    const float* in_feat = (const float*)d_in[0];
    const float* W1 = (const float*)d_in[1];
    const float* b1 = (const float*)d_in[2];
    const float* W2 = (const float*)d_in[3];
    const float* b2 = (const float*)d_in[4];
    const float* W3 = (const float*)d_in[5];
    const float* b3 = (const float*)d_in[6];
    const int*   src = (const int*)d_in[7];
    const int*   dst = (const int*)d_in[8];
    float* out = (float*)d_out;

    float *y, *h;
    int *row_ptr, *cursor, *cnt, *col, *partials;
    cudaGetSymbolAddress((void**)&y, g_y);
    cudaGetSymbolAddress((void**)&h, g_h);
    cudaGetSymbolAddress((void**)&row_ptr, g_row_ptr);
    cudaGetSymbolAddress((void**)&cursor, g_cursor);
    cudaGetSymbolAddress((void**)&cnt, g_cnt);
    cudaGetSymbolAddress((void**)&col, g_col);
    cudaGetSymbolAddress((void**)&partials, g_partials);

    const int smem128 = (64 * (64 + 4) + 64 * (128 + 4)) * (int)sizeof(float);  // ~51KB
    const int smem64  = (64 * (64 + 4) + 64 * (64 + 4))  * (int)sizeof(float);  // ~35KB
    cudaFuncSetAttribute(gemm_kernel<128>,
                         cudaFuncAttributeMaxDynamicSharedMemorySize, smem128);
    cudaFuncSetAttribute(gemm_kernel<64>,
                         cudaFuncAttributeMaxDynamicSharedMemorySize, smem64);

    const int edge4_blocks = (N_EDGES / 4 + 255) / 256;
    const int gemm_blocks  = (N_NODES + 63) / 64;
    const int agg_blocks   = (N_NODES * 32 + 255) / 256;

    // ---- CSR + layer-1 GEMM ----
    cudaMemsetAsync(cnt, 0, N_NODES * sizeof(int), 0);
    hist_kernel<<<edge4_blocks, 256>>>(dst, cnt);                       // 1
    scan_block_kernel<<<SCAN_NBLK, SCAN_B>>>(cnt, row_ptr, partials);   // 2
    scan_add_kernel<<<SCAN_NBLK, SCAN_B>>>(row_ptr, cursor, partials);  // 3
    gemm_kernel<128><<<gemm_blocks, 128, smem128>>>(in_feat, W1, y);    // 4 <- ncu
    fill_kernel<<<edge4_blocks, 256>>>(src, dst, cursor, col);          // 5

    // ---- Layer 1 boundary: h = relu(y + Ay + b1) ----
    aggregate128_kernel<<<agg_blocks, 256>>>(y, row_ptr, col, b1, h);   // 6

    // ---- Layer 2: y = h @ W2 ; h = relu(y + Ay + b2) ----
    gemm_kernel<128><<<gemm_blocks, 128, smem128>>>(h, W2, y);          // 7
    aggregate128_kernel<<<agg_blocks, 256>>>(y, row_ptr, col, b2, h);   // 8

    // ---- Layer 3: y = h @ W3 (64) ; out = relu(y + Ay + b3) ----
    gemm_kernel<64><<<gemm_blocks, 128, smem64>>>(h, W3, y);            // 9
    aggregate64_kernel<<<agg_blocks, 256>>>(y, row_ptr, col, b3, out);  // 10
}

// round 14
// speedup vs baseline: 1.8044x; 1.0020x over previous
#include <cuda_runtime.h>
#include <cstdint>

#define N_NODES 50000
#define N_EDGES 800000
#define D 128
#define NCLS 64
#define SCAN_B 1024
#define SCAN_NBLK ((N_NODES + SCAN_B - 1) / SCAN_B)   // 49

// ---------------------------------------------------------------------------
// Device-global scratch
// ---------------------------------------------------------------------------
__device__ __align__(16) float g_y[N_NODES * D];
__device__ __align__(16) float g_h[N_NODES * D];
__device__ int g_row_ptr[N_NODES + 1];
__device__ int g_cursor[N_NODES];
__device__ int g_cnt[N_NODES];
__device__ int g_col[N_EDGES];
__device__ int g_partials[SCAN_NBLK];

// ---------------------------------------------------------------------------
// CSR kernels (unchanged)
// ---------------------------------------------------------------------------
__global__ void __launch_bounds__(256) hist_kernel(
    const int* __restrict__ dst, int* __restrict__ cnt)
{
    int base = (blockIdx.x * blockDim.x + threadIdx.x) * 4;
    if (base + 3 < N_EDGES) {
        int4 d4 = *reinterpret_cast<const int4*>(dst + base);
        atomicAdd(cnt + d4.x, 1);
        atomicAdd(cnt + d4.y, 1);
        atomicAdd(cnt + d4.z, 1);
        atomicAdd(cnt + d4.w, 1);
    } else {
        for (int e = base; e < N_EDGES; e++) atomicAdd(cnt + dst[e], 1);
    }
}

__global__ void __launch_bounds__(SCAN_B) scan_block_kernel(
    const int* __restrict__ cnt, int* __restrict__ row_ptr, int* __restrict__ partials)
{
    __shared__ int wsum[32];
    int i = blockIdx.x * SCAN_B + threadIdx.x;
    int lane = threadIdx.x & 31;
    int wid  = threadIdx.x >> 5;

    int v = (i < N_NODES) ? cnt[i] : 0;
    int x = v;
    #pragma unroll
    for (int off = 1; off < 32; off <<= 1) {
        int t = __shfl_up_sync(0xffffffffu, x, off);
        if (lane >= off) x += t;
    }
    if (lane == 31) wsum[wid] = x;
    __syncthreads();
    if (wid == 0) {
        int w = wsum[lane];
        #pragma unroll
        for (int off = 1; off < 32; off <<= 1) {
            int t = __shfl_up_sync(0xffffffffu, w, off);
            if (lane >= off) w += t;
        }
        wsum[lane] = w;
    }
    __syncthreads();

    int excl = x - v + (wid ? wsum[wid - 1] : 0);
    if (i < N_NODES) row_ptr[i] = excl;
    if (threadIdx.x == SCAN_B - 1) partials[blockIdx.x] = excl + v;
}

__global__ void __launch_bounds__(SCAN_B) scan_add_kernel(
    int* __restrict__ row_ptr, int* __restrict__ cursor, const int* __restrict__ partials)
{
    __shared__ int sp[SCAN_NBLK];
    if (threadIdx.x < SCAN_NBLK) sp[threadIdx.x] = partials[threadIdx.x];
    __syncthreads();
    if (threadIdx.x == 0) {
        int run = 0;
        #pragma unroll
        for (int k = 0; k < SCAN_NBLK; k++) { int t = sp[k]; sp[k] = run; run += t; }
    }
    __syncthreads();

    int i = blockIdx.x * SCAN_B + threadIdx.x;
    if (i < N_NODES) {
        int r = row_ptr[i] + sp[blockIdx.x];
        row_ptr[i] = r;
        cursor[i]  = r;
    }
    if (i == 0) row_ptr[N_NODES] = N_EDGES;
}

__global__ void __launch_bounds__(256) fill_kernel(
    const int* __restrict__ src, const int* __restrict__ dst,
    int* __restrict__ cursor, int* __restrict__ col)
{
    int base = (blockIdx.x * blockDim.x + threadIdx.x) * 4;
    if (base + 3 < N_EDGES) {
        int4 d4 = *reinterpret_cast<const int4*>(dst + base);
        int4 s4 = *reinterpret_cast<const int4*>(src + base);
        int p0 = atomicAdd(cursor + d4.x, 1);
        int p1 = atomicAdd(cursor + d4.y, 1);
        int p2 = atomicAdd(cursor + d4.z, 1);
        int p3 = atomicAdd(cursor + d4.w, 1);
        col[p0] = s4.x; col[p1] = s4.y; col[p2] = s4.z; col[p3] = s4.w;
    } else {
        for (int e = base; e < N_EDGES; e++) {
            int pos = atomicAdd(cursor + dst[e], 1);
            col[pos] = src[e];
        }
    }
}

// ---------------------------------------------------------------------------
// f32x2 GEMM — R13 kernel with ONE change: __launch_bounds__(128, 4).
// Live state ~120 regs fits the 128-reg cap (unlike R10's 16-col tile), so a
// 4th block/SM = 16 warps (4/SMSP) covers the LDS->FMA latency windows that
// R13's profile (issue 33.7%, no pipe saturated) showed were the bottleneck.
// smem 4 x 51KB = 205KB <= 228KB carveout.
// y[n,j] = sum_k A[n,k] * W[j,k]
// ---------------------------------------------------------------------------
template <int NOUT>
__global__ void __launch_bounds__(128, 4) gemm_kernel(
    const float* __restrict__ A, const float* __restrict__ W, float* __restrict__ y)
{
    constexpr int BM   = 64;
    constexpr int KC   = 64;
    constexpr int TX   = NOUT / 8;        // 16 or 8
    constexpr int TY   = 128 / TX;        // 8 or 16
    constexpr int RPT  = BM / TY;         // 8 or 4
    constexpr int SXS  = KC + 4;          // 68
    constexpr int SWS  = NOUT + 4;        // 132 or 68
    constexpr int HALF = NOUT / 2;        // 64 or 32

    extern __shared__ float smem[];
    float* sX = smem;                     // [BM][SXS]
    float* sW = smem + BM * SXS;          // [KC][SWS]  (W chunk, transposed)

    const int tid  = threadIdx.x;
    const int row0 = blockIdx.x * BM;

    const int tx = tid % TX;
    const int ty = tid / TX;
    const int cb0 = tx * 4;               // first 4-col group
    const int cb1 = HALF + tx * 4;        // second 4-col group
    const int rbase = ty * RPT;

    unsigned long long acc[RPT][4];
    #pragma unroll
    for (int r = 0; r < RPT; r++)
        #pragma unroll
        for (int c = 0; c < 4; c++) acc[r][c] = 0ULL;

    #pragma unroll
    for (int kc = 0; kc < D; kc += KC) {
        // X tile chunk: [BM][KC], coalesced float4 loads
        #pragma unroll
        for (int i = tid; i < BM * (KC / 4); i += 128) {
            int r  = i >> 4;              // KC/4 == 16
            int c4 = i & 15;
            int gr = row0 + r;
            float4 v = make_float4(0.f, 0.f, 0.f, 0.f);
            if (gr < N_NODES)
                v = *reinterpret_cast<const float4*>(A + (size_t)gr * D + kc + c4 * 4);
            reinterpret_cast<float4*>(sX + r * SXS)[c4] = v;
        }
        // W chunk transposed into sW[k][n]
        #pragma unroll
        for (int i = tid; i < NOUT * (KC / 4); i += 128) {
            int n  = i >> 4;
            int k4 = i & 15;
            float4 v = *reinterpret_cast<const float4*>(W + (size_t)n * D + kc + k4 * 4);
            sW[(k4 * 4 + 0) * SWS + n] = v.x;
            sW[(k4 * 4 + 1) * SWS + n] = v.y;
            sW[(k4 * 4 + 2) * SWS + n] = v.z;
            sW[(k4 * 4 + 3) * SWS + n] = v.w;
        }
        __syncthreads();

        #pragma unroll 2
        for (int k4 = 0; k4 < KC; k4 += 4) {
            // a: one LDS.128 per row covering 4 k's (broadcast across tx)
            float4 av[RPT];
            #pragma unroll
            for (int r = 0; r < RPT; r++)
                av[r] = *reinterpret_cast<const float4*>(sX + (rbase + r) * SXS + k4);

            #pragma unroll
            for (int kk = 0; kk < 4; kk++) {
                const float* swk = sW + (k4 + kk) * SWS;
                ulonglong2 b0 = *reinterpret_cast<const ulonglong2*>(swk + cb0);
                ulonglong2 b1 = *reinterpret_cast<const ulonglong2*>(swk + cb1);
                #pragma unroll
                for (int r = 0; r < RPT; r++) {
                    float a = (kk == 0) ? av[r].x : (kk == 1) ? av[r].y
                            : (kk == 2) ? av[r].z : av[r].w;
                    unsigned long long a2;
                    asm("mov.b64 %0, {%1, %1};" : "=l"(a2) : "f"(a));
                    asm("fma.rn.f32x2 %0, %1, %2, %0;" : "+l"(acc[r][0]) : "l"(a2), "l"(b0.x));
                    asm("fma.rn.f32x2 %0, %1, %2, %0;" : "+l"(acc[r][1]) : "l"(a2), "l"(b0.y));
                    asm("fma.rn.f32x2 %0, %1, %2, %0;" : "+l"(acc[r][2]) : "l"(a2), "l"(b1.x));
                    asm("fma.rn.f32x2 %0, %1, %2, %0;" : "+l"(acc[r][3]) : "l"(a2), "l"(b1.y));
                }
            }
        }
        __syncthreads();
    }

    #pragma unroll
    for (int r = 0; r < RPT; r++) {
        int row = row0 + rbase + r;
        if (row >= N_NODES) continue;
        float o[8];
        #pragma unroll
        for (int c = 0; c < 4; c++)
            asm("mov.b64 {%0, %1}, %2;" : "=f"(o[2*c]), "=f"(o[2*c+1]) : "l"(acc[r][c]));
        *reinterpret_cast<float4*>(y + (size_t)row * NOUT + cb0) =
            make_float4(o[0], o[1], o[2], o[3]);
        *reinterpret_cast<float4*>(y + (size_t)row * NOUT + cb1) =
            make_float4(o[4], o[5], o[6], o[7]);
    }
}

// ---------------------------------------------------------------------------
// CSR aggregation + bias + relu (unchanged: unroll-4, warp per node)
// ---------------------------------------------------------------------------
__global__ void __launch_bounds__(256) aggregate128_kernel(
    const float* __restrict__ y, const int* __restrict__ row_ptr,
    const int* __restrict__ col, const float* __restrict__ bias,
    float* __restrict__ out)
{
    int node = (blockIdx.x * blockDim.x + threadIdx.x) >> 5;
    int lane = threadIdx.x & 31;
    if (node >= N_NODES) return;

    int beg = __ldg(row_ptr + node);
    int end = __ldg(row_ptr + node + 1);

    const float4* base = reinterpret_cast<const float4*>(y);
    float4 acc = base[(size_t)node * 32 + lane];
    float4 acc2 = make_float4(0.f, 0.f, 0.f, 0.f);

    int j = beg;
    for (; j + 3 < end; j += 4) {
        int c0 = __ldg(col + j);
        int c1 = __ldg(col + j + 1);
        int c2 = __ldg(col + j + 2);
        int c3 = __ldg(col + j + 3);
        float4 v0 = base[(size_t)c0 * 32 + lane];
        float4 v1 = base[(size_t)c1 * 32 + lane];
        float4 v2 = base[(size_t)c2 * 32 + lane];
        float4 v3 = base[(size_t)c3 * 32 + lane];
        acc.x  += v0.x; acc.y  += v0.y; acc.z  += v0.z; acc.w  += v0.w;
        acc2.x += v1.x; acc2.y += v1.y; acc2.z += v1.z; acc2.w += v1.w;
        acc.x  += v2.x; acc.y  += v2.y; acc.z  += v2.z; acc.w  += v2.w;
        acc2.x += v3.x; acc2.y += v3.y; acc2.z += v3.z; acc2.w += v3.w;
    }
    for (; j < end; j++) {
        int c0 = __ldg(col + j);
        float4 v0 = base[(size_t)c0 * 32 + lane];
        acc.x += v0.x; acc.y += v0.y; acc.z += v0.z; acc.w += v0.w;
    }
    acc.x += acc2.x; acc.y += acc2.y; acc.z += acc2.z; acc.w += acc2.w;

    float4 b = reinterpret_cast<const float4*>(bias)[lane];
    float4 o;
    o.x = fmaxf(acc.x + b.x, 0.f);
    o.y = fmaxf(acc.y + b.y, 0.f);
    o.z = fmaxf(acc.z + b.z, 0.f);
    o.w = fmaxf(acc.w + b.w, 0.f);
    reinterpret_cast<float4*>(out)[(size_t)node * 32 + lane] = o;
}

__global__ void __launch_bounds__(256) aggregate64_kernel(
    const float* __restrict__ y, const int* __restrict__ row_ptr,
    const int* __restrict__ col, const float* __restrict__ bias,
    float* __restrict__ out)
{
    int node = (blockIdx.x * blockDim.x + threadIdx.x) >> 5;
    int lane = threadIdx.x & 31;
    if (node >= N_NODES) return;

    int beg = __ldg(row_ptr + node);
    int end = __ldg(row_ptr + node + 1);

    const float2* base = reinterpret_cast<const float2*>(y);
    float2 acc = base[(size_t)node * 32 + lane];
    float2 acc2 = make_float2(0.f, 0.f);

    int j = beg;
    for (; j + 3 < end; j += 4) {
        int c0 = __ldg(col + j);
        int c1 = __ldg(col + j + 1);
        int c2 = __ldg(col + j + 2);
        int c3 = __ldg(col + j + 3);
        float2 v0 = base[(size_t)c0 * 32 + lane];
        float2 v1 = base[(size_t)c1 * 32 + lane];
        float2 v2 = base[(size_t)c2 * 32 + lane];
        float2 v3 = base[(size_t)c3 * 32 + lane];
        acc.x  += v0.x; acc.y  += v0.y;
        acc2.x += v1.x; acc2.y += v1.y;
        acc.x  += v2.x; acc.y  += v2.y;
        acc2.x += v3.x; acc2.y += v3.y;
    }
    for (; j < end; j++) {
        int c0 = __ldg(col + j);
        float2 v0 = base[(size_t)c0 * 32 + lane];
        acc.x += v0.x; acc.y += v0.y;
    }
    acc.x += acc2.x; acc.y += acc2.y;

    float2 b = reinterpret_cast<const float2*>(bias)[lane];
    float2 o;
    o.x = fmaxf(acc.x + b.x, 0.f);
    o.y = fmaxf(acc.y + b.y, 0.f);
    reinterpret_cast<float2*>(out)[(size_t)node * 32 + lane] = o;
}

// ---------------------------------------------------------------------------
// Launch: single stream, gemm1 in slot 4 (ncu lands there)
// ---------------------------------------------------------------------------
extern "C" void kernel_launch(void* const* d_in, const int* in_sizes, int n_in,
                              void* d_out, int out_size)
{
    const float* in_feat = (const float*)d_in[0];
    const float* W1 = (const float*)d_in[1];
    const float* b1 = (const float*)d_in[2];
    const float* W2 = (const float*)d_in[3];
    const float* b2 = (const float*)d_in[4];
    const float* W3 = (const float*)d_in[5];
    const float* b3 = (const float*)d_in[6];
    const int*   src = (const int*)d_in[7];
    const int*   dst = (const int*)d_in[8];
    float* out = (float*)d_out;

    float *y, *h;
    int *row_ptr, *cursor, *cnt, *col, *partials;
    cudaGetSymbolAddress((void**)&y, g_y);
    cudaGetSymbolAddress((void**)&h, g_h);
    cudaGetSymbolAddress((void**)&row_ptr, g_row_ptr);
    cudaGetSymbolAddress((void**)&cursor, g_cursor);
    cudaGetSymbolAddress((void**)&cnt, g_cnt);
    cudaGetSymbolAddress((void**)&col, g_col);
    cudaGetSymbolAddress((void**)&partials, g_partials);

    const int smem128 = (64 * (64 + 4) + 64 * (128 + 4)) * (int)sizeof(float);  // ~51KB
    const int smem64  = (64 * (64 + 4) + 64 * (64 + 4))  * (int)sizeof(float);  // ~35KB
    cudaFuncSetAttribute(gemm_kernel<128>,
                         cudaFuncAttributeMaxDynamicSharedMemorySize, smem128);
    cudaFuncSetAttribute(gemm_kernel<64>,
                         cudaFuncAttributeMaxDynamicSharedMemorySize, smem64);

    const int edge4_blocks = (N_EDGES / 4 + 255) / 256;
    const int gemm_blocks  = (N_NODES + 63) / 64;
    const int agg_blocks   = (N_NODES * 32 + 255) / 256;

    // ---- CSR + layer-1 GEMM ----
    cudaMemsetAsync(cnt, 0, N_NODES * sizeof(int), 0);
    hist_kernel<<<edge4_blocks, 256>>>(dst, cnt);                       // 1
    scan_block_kernel<<<SCAN_NBLK, SCAN_B>>>(cnt, row_ptr, partials);   // 2
    scan_add_kernel<<<SCAN_NBLK, SCAN_B>>>(row_ptr, cursor, partials);  // 3
    gemm_kernel<128><<<gemm_blocks, 128, smem128>>>(in_feat, W1, y);    // 4 <- ncu
    fill_kernel<<<edge4_blocks, 256>>>(src, dst, cursor, col);          // 5

    // ---- Layer 1 boundary: h = relu(y + Ay + b1) ----
    aggregate128_kernel<<<agg_blocks, 256>>>(y, row_ptr, col, b1, h);   // 6

    // ---- Layer 2: y = h @ W2 ; h = relu(y + Ay + b2) ----
    gemm_kernel<128><<<gemm_blocks, 128, smem128>>>(h, W2, y);          // 7
    aggregate128_kernel<<<agg_blocks, 256>>>(y, row_ptr, col, b2, h);   // 8

    // ---- Layer 3: y = h @ W3 (64) ; out = relu(y + Ay + b3) ----
    gemm_kernel<64><<<gemm_blocks, 128, smem64>>>(h, W3, y);            // 9
    aggregate64_kernel<<<agg_blocks, 256>>>(y, row_ptr, col, b3, out);  // 10
}